// round 8
// baseline (speedup 1.0000x reference)
#include <cuda_runtime.h>
#include <cuda_fp16.h>

#define NN 50000
#define EE 800000

typedef unsigned long long ull;

__device__ __forceinline__ void ffma2(ull &d, ull a, ull b) {
    asm("fma.rn.f32x2 %0, %1, %2, %0;" : "+l"(d) : "l"(a), "l"(b));
}
__device__ __forceinline__ ull pack2(float a, float b) {
    ull r; asm("mov.b64 %0, {%1, %2};" : "=l"(r) : "f"(a), "f"(b)); return r;
}
__device__ __forceinline__ float lo2(ull u) { return __uint_as_float((unsigned)u); }
__device__ __forceinline__ float hi2(ull u) { return __uint_as_float((unsigned)(u >> 32)); }

// ---------------- scratch ----------------
__device__ float g_dinv[NN];
__device__ int   g_indeg[NN];
__device__ int   g_cur[NN];
__device__ int   g_off[NN + 1];
__device__ int   g_adj[EE];
__device__ int   g_bsum[64];

__device__ __half g_y0h[NN * 64];    // fp16 dinv*x
__device__ float  g_ax[NN * 64];
__device__ float  g_raw1[NN * 128];
__device__ __half g_y1h[NN * 128];   // fp16 dinv*act1
__device__ float  g_agg1[NN * 128];
__device__ float  g_raw2[NN * 256];
__device__ __half g_y3h[NN * 64];    // fp16 dinv*(act2@W3)

__device__ float g_ssum[512];
__device__ float g_ssq[512];

// ---------------- setup ----------------
__global__ void k_zero() {
    int i = blockIdx.x * blockDim.x + threadIdx.x;
    if (i < NN) { g_indeg[i] = 0; g_cur[i] = 0; }
    if (i < 512) { g_ssum[i] = 0.f; g_ssq[i] = 0.f; }
}

__global__ void k_indeg(const int* __restrict__ dst) {
    int e = blockIdx.x * blockDim.x + threadIdx.x;
    if (e < EE) atomicAdd(&g_indeg[dst[e]], 1);
}

__global__ void k_dinv_y0(const float* __restrict__ x) {
    int idx = blockIdx.x * blockDim.x + threadIdx.x;
    if (idx < NN * 16) {
        int row = idx >> 4;
        float d = rsqrtf((float)(g_indeg[row] + 1));
        if ((idx & 15) == 0) g_dinv[row] = d;
        float4 v = ((const float4*)x)[idx];
        __half2 h0 = __floats2half2_rn(v.x * d, v.y * d);
        __half2 h1 = __floats2half2_rn(v.z * d, v.w * d);
        ((uint2*)g_y0h)[idx] = make_uint2(*(unsigned*)&h0, *(unsigned*)&h1);
    }
}

// ---------------- CSR build ----------------
__global__ void k_scan1() {
    int i = blockIdx.x * 1024 + threadIdx.x;
    int v = (i < NN) ? g_indeg[i] : 0;
    int lane = threadIdx.x & 31, wid = threadIdx.x >> 5;
    int s = v;
    #pragma unroll
    for (int o = 1; o < 32; o <<= 1) {
        int t = __shfl_up_sync(~0u, s, o);
        if (lane >= o) s += t;
    }
    __shared__ int wsum[32];
    if (lane == 31) wsum[wid] = s;
    __syncthreads();
    if (wid == 0) {
        int ws = wsum[lane];
        #pragma unroll
        for (int o = 1; o < 32; o <<= 1) {
            int t = __shfl_up_sync(~0u, ws, o);
            if (lane >= o) ws += t;
        }
        wsum[lane] = ws;
    }
    __syncthreads();
    int incl = s + (wid > 0 ? wsum[wid - 1] : 0);
    if (i < NN) g_off[i + 1] = incl;
    if (threadIdx.x == 1023) g_bsum[blockIdx.x] = incl;
}

__global__ void k_scan3() {
    __shared__ int base;
    if (threadIdx.x == 0) {
        int acc = 0;
        for (int b = 0; b < blockIdx.x; b++) acc += g_bsum[b];
        base = acc;
    }
    __syncthreads();
    int i = blockIdx.x * 1024 + threadIdx.x;
    if (i < NN) g_off[i + 1] += base;
    if (i == 0) g_off[0] = 0;
}

__global__ void k_scatter(const int* __restrict__ src, const int* __restrict__ dst) {
    int e = blockIdx.x * blockDim.x + threadIdx.x;
    if (e < EE) {
        int d = dst[e];
        int p = g_off[d] + atomicAdd(&g_cur[d], 1);
        g_adj[p] = src[e];
    }
}

// ---------------- layer-1 aggregation: fp16 gather, 4-deep index batching ----------------
__global__ void k_agg1h(const __half* __restrict__ y, float* __restrict__ out) {
    int gw = (blockIdx.x * blockDim.x + threadIdx.x) >> 5;
    if (gw >= NN) return;
    int lane = threadIdx.x & 31;
    int beg = g_off[gw], end = g_off[gw + 1];
    float2 acc = __half22float2(*(const __half2*)(y + gw * 64 + lane * 2));
    int j = beg;
    for (; j + 4 <= end; j += 4) {
        int s0 = __ldg(&g_adj[j]);
        int s1 = __ldg(&g_adj[j + 1]);
        int s2 = __ldg(&g_adj[j + 2]);
        int s3 = __ldg(&g_adj[j + 3]);
        float2 v0 = __half22float2(__ldg((const __half2*)(y + s0 * 64 + lane * 2)));
        float2 v1 = __half22float2(__ldg((const __half2*)(y + s1 * 64 + lane * 2)));
        float2 v2 = __half22float2(__ldg((const __half2*)(y + s2 * 64 + lane * 2)));
        float2 v3 = __half22float2(__ldg((const __half2*)(y + s3 * 64 + lane * 2)));
        acc.x += (v0.x + v1.x) + (v2.x + v3.x);
        acc.y += (v0.y + v1.y) + (v2.y + v3.y);
    }
    for (; j < end; j++) {
        int s = __ldg(&g_adj[j]);
        float2 v = __half22float2(__ldg((const __half2*)(y + s * 64 + lane * 2)));
        acc.x += v.x; acc.y += v.y;
    }
    float d = g_dinv[gw];
    acc.x *= d; acc.y *= d;
    *(float2*)(out + gw * 64 + lane * 2) = acc;
}

// ---------------- layer-2 aggregation: fp16 gather (4 cols/lane), 4-deep batching ----------------
__global__ void k_agg2h(const __half* __restrict__ y, float* __restrict__ out) {
    int gw = (blockIdx.x * blockDim.x + threadIdx.x) >> 5;
    if (gw >= NN) return;
    int lane = threadIdx.x & 31;
    int beg = g_off[gw], end = g_off[gw + 1];
    uint2 u0 = *(const uint2*)(y + (size_t)gw * 128 + lane * 4);
    float2 a01 = __half22float2(*(__half2*)&u0.x);
    float2 a23 = __half22float2(*(__half2*)&u0.y);
    float4 acc = make_float4(a01.x, a01.y, a23.x, a23.y);
    int j = beg;
    for (; j + 4 <= end; j += 4) {
        int s0 = __ldg(&g_adj[j]);
        int s1 = __ldg(&g_adj[j + 1]);
        int s2 = __ldg(&g_adj[j + 2]);
        int s3 = __ldg(&g_adj[j + 3]);
        uint2 q0 = __ldg((const uint2*)(y + (size_t)s0 * 128 + lane * 4));
        uint2 q1 = __ldg((const uint2*)(y + (size_t)s1 * 128 + lane * 4));
        uint2 q2 = __ldg((const uint2*)(y + (size_t)s2 * 128 + lane * 4));
        uint2 q3 = __ldg((const uint2*)(y + (size_t)s3 * 128 + lane * 4));
        float2 f;
        f = __half22float2(*(__half2*)&q0.x); acc.x += f.x; acc.y += f.y;
        f = __half22float2(*(__half2*)&q0.y); acc.z += f.x; acc.w += f.y;
        f = __half22float2(*(__half2*)&q1.x); acc.x += f.x; acc.y += f.y;
        f = __half22float2(*(__half2*)&q1.y); acc.z += f.x; acc.w += f.y;
        f = __half22float2(*(__half2*)&q2.x); acc.x += f.x; acc.y += f.y;
        f = __half22float2(*(__half2*)&q2.y); acc.z += f.x; acc.w += f.y;
        f = __half22float2(*(__half2*)&q3.x); acc.x += f.x; acc.y += f.y;
        f = __half22float2(*(__half2*)&q3.y); acc.z += f.x; acc.w += f.y;
    }
    for (; j < end; j++) {
        int s = __ldg(&g_adj[j]);
        uint2 u = __ldg((const uint2*)(y + (size_t)s * 128 + lane * 4));
        float2 f01 = __half22float2(*(__half2*)&u.x);
        float2 f23 = __half22float2(*(__half2*)&u.y);
        acc.x += f01.x; acc.y += f01.y; acc.z += f23.x; acc.w += f23.y;
    }
    float d = g_dinv[gw];
    acc.x *= d; acc.y *= d; acc.z *= d; acc.w *= d;
    *(float4*)(out + (size_t)gw * 128 + lane * 4) = acc;
}

// ---------------- layer-3 aggregation (fp16 gather, 4-deep) + final epilogue ----------------
__global__ void k_agg3f(const __half* __restrict__ y, float* __restrict__ out_mu,
                        const float* __restrict__ bm3, const float* __restrict__ bl3,
                        float* __restrict__ out_ls) {
    int gw = (blockIdx.x * blockDim.x + threadIdx.x) >> 5;
    if (gw >= NN) return;
    int lane = threadIdx.x & 31;
    int beg = g_off[gw], end = g_off[gw + 1];
    float2 acc = __half22float2(*(const __half2*)(y + gw * 64 + lane * 2));
    int j = beg;
    for (; j + 4 <= end; j += 4) {
        int s0 = __ldg(&g_adj[j]);
        int s1 = __ldg(&g_adj[j + 1]);
        int s2 = __ldg(&g_adj[j + 2]);
        int s3 = __ldg(&g_adj[j + 3]);
        float2 v0 = __half22float2(__ldg((const __half2*)(y + s0 * 64 + lane * 2)));
        float2 v1 = __half22float2(__ldg((const __half2*)(y + s1 * 64 + lane * 2)));
        float2 v2 = __half22float2(__ldg((const __half2*)(y + s2 * 64 + lane * 2)));
        float2 v3 = __half22float2(__ldg((const __half2*)(y + s3 * 64 + lane * 2)));
        acc.x += (v0.x + v1.x) + (v2.x + v3.x);
        acc.y += (v0.y + v1.y) + (v2.y + v3.y);
    }
    for (; j < end; j++) {
        int s = __ldg(&g_adj[j]);
        float2 v = __half22float2(__ldg((const __half2*)(y + s * 64 + lane * 2)));
        acc.x += v.x; acc.y += v.y;
    }
    float d = g_dinv[gw];
    acc.x *= d; acc.y *= d;
    int c = lane * 2;
    if (c < 32) {
        out_mu[gw * 32 + c]     = acc.x + bm3[c];
        out_mu[gw * 32 + c + 1] = acc.y + bm3[c + 1];
    } else {
        out_ls[gw * 32 + c - 32] = fminf(acc.x + bl3[c - 32], 10.0f);
        out_ls[gw * 32 + c - 31] = fminf(acc.y + bl3[c - 31], 10.0f);
    }
}

// ---------------- layer-1 GEMM: row-pair FFMA2 ----------------
__global__ void __launch_bounds__(256) k_gemm1(
        const float* __restrict__ A, const float* __restrict__ W1,
        const float* __restrict__ W2, const float* __restrict__ b1,
        const float* __restrict__ b2, float* __restrict__ C) {
    extern __shared__ float sm1[];
    float* Ws  = sm1;
    float* Ast = sm1 + 8192;
    int tid = threadIdx.x;
    int row0 = blockIdx.x * 64;

    for (int i = tid; i < 1024; i += 256) {
        int k = i >> 4, q = i & 15;
        ((float4*)(Ws + k * 128))[q]      = ((const float4*)(W1 + k * 64))[q];
        ((float4*)(Ws + k * 128 + 64))[q] = ((const float4*)(W2 + k * 64))[q];
    }
    for (int i = tid; i < 1024; i += 256) {
        int r = i >> 4, q = i & 15;
        float4 v = make_float4(0.f, 0.f, 0.f, 0.f);
        if (row0 + r < NN) v = ((const float4*)(A + (row0 + r) * 64))[q];
        int k = q * 4;
        Ast[(k + 0) * 66 + r] = v.x;
        Ast[(k + 1) * 66 + r] = v.y;
        Ast[(k + 2) * 66 + r] = v.z;
        Ast[(k + 3) * 66 + r] = v.w;
    }
    __syncthreads();

    int tx = tid & 31, ty = tid >> 5;
    ull acc[4][4];
    #pragma unroll
    for (int i = 0; i < 4; i++)
        #pragma unroll
        for (int j = 0; j < 4; j++) acc[i][j] = 0ull;

    #pragma unroll 8
    for (int k = 0; k < 64; k++) {
        ull a2[4], w2[4];
        #pragma unroll
        for (int i = 0; i < 4; i++)
            a2[i] = *(const ull*)(Ast + k * 66 + ty * 8 + 2 * i);
        #pragma unroll
        for (int j = 0; j < 4; j++) {
            float w = Ws[k * 128 + tx + 32 * j];
            w2[j] = pack2(w, w);
        }
        #pragma unroll
        for (int i = 0; i < 4; i++)
            #pragma unroll
            for (int j = 0; j < 4; j++)
                ffma2(acc[i][j], a2[i], w2[j]);
    }

    float bb[4];
    bb[0] = b1[tx]; bb[1] = b1[tx + 32]; bb[2] = b2[tx]; bb[3] = b2[tx + 32];

    float ls[4] = {0.f, 0.f, 0.f, 0.f}, l2[4] = {0.f, 0.f, 0.f, 0.f};
    #pragma unroll
    for (int i = 0; i < 4; i++) {
        int r = row0 + ty * 8 + 2 * i;
        #pragma unroll
        for (int h = 0; h < 2; h++) {
            if (r + h < NN) {
                #pragma unroll
                for (int j = 0; j < 4; j++) {
                    float v = (h == 0 ? lo2(acc[i][j]) : hi2(acc[i][j])) + bb[j];
                    C[(size_t)(r + h) * 128 + tx + 32 * j] = v;
                    float sv = (j < 2) ? v : fmaxf(v, 0.f);
                    ls[j] += sv; l2[j] += sv * sv;
                }
            }
        }
    }
    __syncthreads();
    float* red = Ast;
    red[tid] = 0.f;
    __syncthreads();
    #pragma unroll
    for (int j = 0; j < 4; j++) {
        atomicAdd(&red[tx + 32 * j], ls[j]);
        atomicAdd(&red[128 + tx + 32 * j], l2[j]);
    }
    __syncthreads();
    if (tid < 128) {
        atomicAdd(&g_ssum[tid], red[tid]);
        atomicAdd(&g_ssq[tid], red[tid + 128]);
    }
}

// elementwise layer1 -> fp16 y1h, statfin folded
__global__ void k_ew1(const float* __restrict__ g1, const float* __restrict__ h1,
                      const float* __restrict__ g2, const float* __restrict__ h2) {
    __shared__ float sa[128], sb[128];
    int tid = threadIdx.x;
    if (tid < 128) {
        float m = g_ssum[tid] * (1.0f / NN);
        float v = g_ssq[tid] * (1.0f / NN) - m * m;
        float rstd = rsqrtf(v + 1e-5f);
        float gamma = (tid < 64) ? g1[tid] : g2[tid - 64];
        float beta  = (tid < 64) ? h1[tid] : h2[tid - 64];
        float a = gamma * rstd;
        sa[tid] = a;
        sb[tid] = beta - m * a;
    }
    __syncthreads();
    int idx = blockIdx.x * blockDim.x + tid;
    if (idx >= NN * 32) return;
    int r = idx >> 5;
    int c4 = (idx & 31) << 2;
    float4 v = ((const float4*)g_raw1)[idx];
    float d = g_dinv[r];
    float o[4]; float vv[4] = {v.x, v.y, v.z, v.w};
    #pragma unroll
    for (int t = 0; t < 4; t++) {
        int c = c4 + t;
        float a = sa[c], b = sb[c];
        if (c4 < 64) o[t] = fmaxf(vv[t] * a + b, 0.f);
        else         o[t] = fmaxf(vv[t], 0.f) * a + b;
        o[t] *= d;
    }
    __half2 h0 = __floats2half2_rn(o[0], o[1]);
    __half2 h1v = __floats2half2_rn(o[2], o[3]);
    ((uint2*)g_y1h)[idx] = make_uint2(*(unsigned*)&h0, *(unsigned*)&h1v);
}

// ---------------- layer-2 GEMM: row-pair FFMA2 ----------------
__global__ void __launch_bounds__(256) k_gemm2(
        const float* __restrict__ A, const float* __restrict__ W1,
        const float* __restrict__ W2, const float* __restrict__ b1,
        const float* __restrict__ b2, float* __restrict__ C) {
    extern __shared__ float sm2[];
    float* Ws  = sm2;
    float* Ast = sm2 + 16384;
    int tid = threadIdx.x;
    int row0 = blockIdx.x * 64;

    for (int i = tid; i < 2048; i += 256) {
        int k = i >> 5, q = i & 31;
        ((float4*)(Ws + k * 256))[q]       = ((const float4*)(W1 + k * 128))[q];
        ((float4*)(Ws + k * 256 + 128))[q] = ((const float4*)(W2 + k * 128))[q];
    }
    for (int i = tid; i < 2048; i += 256) {
        int r = i >> 5, q = i & 31;
        float4 v = make_float4(0.f, 0.f, 0.f, 0.f);
        if (row0 + r < NN) v = ((const float4*)(A + (size_t)(row0 + r) * 128))[q];
        int k = q * 4;
        Ast[(k + 0) * 66 + r] = v.x;
        Ast[(k + 1) * 66 + r] = v.y;
        Ast[(k + 2) * 66 + r] = v.z;
        Ast[(k + 3) * 66 + r] = v.w;
    }
    __syncthreads();

    int tx = tid & 31, ty = tid >> 5;
    ull acc[4][8];
    #pragma unroll
    for (int i = 0; i < 4; i++)
        #pragma unroll
        for (int j = 0; j < 8; j++) acc[i][j] = 0ull;

    #pragma unroll 4
    for (int k = 0; k < 64; k++) {
        ull alo[4], ahi[4], w2[8];
        #pragma unroll
        for (int i = 0; i < 4; i++) {
            alo[i] = *(const ull*)(Ast + k * 66 + ty * 8 + 2 * i);
            ahi[i] = *(const ull*)(Ast + (64 + k) * 66 + ty * 8 + 2 * i);
        }
        #pragma unroll
        for (int j = 0; j < 8; j++) {
            float w = Ws[k * 256 + tx + 32 * j];
            w2[j] = pack2(w, w);
        }
        #pragma unroll
        for (int i = 0; i < 4; i++)
            #pragma unroll
            for (int j = 0; j < 8; j++)
                ffma2(acc[i][j], (j < 4 ? alo[i] : ahi[i]), w2[j]);
    }

    float bb[8];
    #pragma unroll
    for (int j = 0; j < 8; j++)
        bb[j] = (j < 4) ? b1[tx + 32 * j] : b2[tx + 32 * j - 128];

    float ls[8], l2[8];
    #pragma unroll
    for (int j = 0; j < 8; j++) { ls[j] = 0.f; l2[j] = 0.f; }
    #pragma unroll
    for (int i = 0; i < 4; i++) {
        int r = row0 + ty * 8 + 2 * i;
        #pragma unroll
        for (int h = 0; h < 2; h++) {
            if (r + h < NN) {
                #pragma unroll
                for (int j = 0; j < 8; j++) {
                    float v = (h == 0 ? lo2(acc[i][j]) : hi2(acc[i][j])) + bb[j];
                    C[(size_t)(r + h) * 256 + tx + 32 * j] = v;
                    float sv = (j < 4) ? v : fmaxf(v, 0.f);
                    ls[j] += sv; l2[j] += sv * sv;
                }
            }
        }
    }
    __syncthreads();
    float* red = Ast;
    red[tid] = 0.f; red[tid + 256] = 0.f;
    __syncthreads();
    #pragma unroll
    for (int j = 0; j < 8; j++) {
        atomicAdd(&red[tx + 32 * j], ls[j]);
        atomicAdd(&red[256 + tx + 32 * j], l2[j]);
    }
    __syncthreads();
    atomicAdd(&g_ssum[256 + tid], red[tid]);
    atomicAdd(&g_ssq[256 + tid], red[tid + 256]);
}

// ---------------- layer-3 GEMM with BN-on-load + folded statfin, fp16 output ----------------
__global__ void __launch_bounds__(256) k_gemm3(
        const float* __restrict__ raw2, const float* __restrict__ Wm3,
        const float* __restrict__ Wl3, __half* __restrict__ y3,
        const float* __restrict__ g1, const float* __restrict__ h1,
        const float* __restrict__ g2, const float* __restrict__ h2) {
    extern __shared__ float sm3[];
    float* sa  = sm3;
    float* sb  = sm3 + 256;
    float* Ws  = sm3 + 512;
    float* Ast = sm3 + 512 + 8192;
    int tid = threadIdx.x;
    int row0 = blockIdx.x * 128;

    {
        float m = g_ssum[256 + tid] * (1.0f / NN);
        float v = g_ssq[256 + tid] * (1.0f / NN) - m * m;
        float rstd = rsqrtf(v + 1e-5f);
        float gamma = (tid < 128) ? g1[tid] : g2[tid - 128];
        float beta  = (tid < 128) ? h1[tid] : h2[tid - 128];
        float a = gamma * rstd;
        sa[tid] = a;
        sb[tid] = beta - m * a;
    }

    for (int i = tid; i < 2048; i += 256) {
        int k = i >> 4, q = i & 15;
        float4 v = (q < 8) ? ((const float4*)(Wm3 + k * 32))[q]
                           : ((const float4*)(Wl3 + k * 32))[q - 8];
        ((float4*)(Ws + k * 64))[q] = v;
    }

    int tx = tid & 15, ty = tid >> 4;
    int half_c = (tx >= 8) ? 1 : 0;
    ull acc[4][4];
    #pragma unroll
    for (int i = 0; i < 4; i++)
        #pragma unroll
        for (int j = 0; j < 4; j++) acc[i][j] = 0ull;

    for (int kt = 0; kt < 128; kt += 32) {
        __syncthreads();
        for (int i = tid; i < 2048; i += 256) {
            int r = i >> 4, q = i & 15;
            int half = q >> 3, kk = (q & 7) << 2;
            float4 v = make_float4(0.f, 0.f, 0.f, 0.f);
            if (row0 + r < NN)
                v = ((const float4*)(raw2 + (size_t)(row0 + r) * 256 + half * 128 + kt))[q & 7];
            float o[4]; float vv[4] = {v.x, v.y, v.z, v.w};
            #pragma unroll
            for (int t = 0; t < 4; t++) {
                int col = half * 128 + kt + kk + t;
                float a = sa[col], b = sb[col];
                if (half == 0) o[t] = fmaxf(vv[t] * a + b, 0.f);
                else           o[t] = fmaxf(vv[t], 0.f) * a + b;
                Ast[(half * 32 + kk + t) * 130 + r] = o[t];
            }
        }
        __syncthreads();
        #pragma unroll 8
        for (int k = 0; k < 32; k++) {
            float4 w = ((float4*)(Ws + (kt + k) * 64))[tx];
            ull w2[4];
            w2[0] = pack2(w.x, w.x); w2[1] = pack2(w.y, w.y);
            w2[2] = pack2(w.z, w.z); w2[3] = pack2(w.w, w.w);
            ull a2[4];
            #pragma unroll
            for (int i = 0; i < 4; i++)
                a2[i] = *(const ull*)(Ast + (half_c * 32 + k) * 130 + ty * 8 + 2 * i);
            #pragma unroll
            for (int i = 0; i < 4; i++)
                #pragma unroll
                for (int j = 0; j < 4; j++)
                    ffma2(acc[i][j], a2[i], w2[j]);
        }
    }
    #pragma unroll
    for (int i = 0; i < 4; i++) {
        int r = row0 + ty * 8 + 2 * i;
        if (r < NN) {
            float d = g_dinv[r];
            __half2 h0 = __floats2half2_rn(lo2(acc[i][0]) * d, lo2(acc[i][1]) * d);
            __half2 h1v = __floats2half2_rn(lo2(acc[i][2]) * d, lo2(acc[i][3]) * d);
            ((uint2*)(y3 + (size_t)r * 64))[tx] = make_uint2(*(unsigned*)&h0, *(unsigned*)&h1v);
        }
        if (r + 1 < NN) {
            float d = g_dinv[r + 1];
            __half2 h0 = __floats2half2_rn(hi2(acc[i][0]) * d, hi2(acc[i][1]) * d);
            __half2 h1v = __floats2half2_rn(hi2(acc[i][2]) * d, hi2(acc[i][3]) * d);
            ((uint2*)(y3 + (size_t)(r + 1) * 64))[tx] = make_uint2(*(unsigned*)&h0, *(unsigned*)&h1v);
        }
    }
}

// ---------------- decoder ----------------
__global__ void k_dec(const int* __restrict__ src, const int* __restrict__ dst,
                      const float* __restrict__ mu, float* __restrict__ probs) {
    int t = blockIdx.x * blockDim.x + threadIdx.x;
    int e = t >> 3, sub = t & 7;
    int s = src[e], d = dst[e];
    float4 a = __ldg((const float4*)(mu + s * 32 + sub * 4));
    float4 b = __ldg((const float4*)(mu + d * 32 + sub * 4));
    float p = a.x * b.x + a.y * b.y + a.z * b.z + a.w * b.w;
    p += __shfl_down_sync(~0u, p, 4);
    p += __shfl_down_sync(~0u, p, 2);
    p += __shfl_down_sync(~0u, p, 1);
    if (sub == 0) probs[e] = 1.f / (1.f + expf(-p));
}

// ---------------- launch ----------------
extern "C" void kernel_launch(void* const* d_in, const int* in_sizes, int n_in,
                              void* d_out, int out_size) {
    const float* x   = (const float*)d_in[0];
    const int* ei    = (const int*)d_in[1];
    const int* src   = ei;
    const int* dst   = ei + EE;
    const float* Wm1 = (const float*)d_in[2];
    const float* bm1 = (const float*)d_in[3];
    const float* gm1 = (const float*)d_in[4];
    const float* hm1 = (const float*)d_in[5];
    const float* Wm2 = (const float*)d_in[6];
    const float* bm2 = (const float*)d_in[7];
    const float* gm2 = (const float*)d_in[8];
    const float* hm2 = (const float*)d_in[9];
    const float* Wm3 = (const float*)d_in[10];
    const float* bm3 = (const float*)d_in[11];
    const float* Wl1 = (const float*)d_in[12];
    const float* bl1 = (const float*)d_in[13];
    const float* gl1 = (const float*)d_in[14];
    const float* hl1 = (const float*)d_in[15];
    const float* Wl2 = (const float*)d_in[16];
    const float* bl2 = (const float*)d_in[17];
    const float* gl2 = (const float*)d_in[18];
    const float* hl2 = (const float*)d_in[19];
    const float* Wl3 = (const float*)d_in[20];
    const float* bl3 = (const float*)d_in[21];

    float* out = (float*)d_out;
    float* out_probs = out;
    float* out_mu = out + EE;
    float* out_ls = out + EE + NN * 32;

    float *ax, *raw1, *agg1, *raw2;
    __half *y0h, *y1h, *y3h;
    cudaGetSymbolAddress((void**)&y0h, g_y0h);
    cudaGetSymbolAddress((void**)&ax, g_ax);
    cudaGetSymbolAddress((void**)&raw1, g_raw1);
    cudaGetSymbolAddress((void**)&y1h, g_y1h);
    cudaGetSymbolAddress((void**)&agg1, g_agg1);
    cudaGetSymbolAddress((void**)&raw2, g_raw2);
    cudaGetSymbolAddress((void**)&y3h, g_y3h);

    const int SM1 = (64 * 128 + 64 * 66) * 4;
    const int SM2 = (64 * 256 + 128 * 66) * 4;
    const int SM3 = (512 + 128 * 64 + 64 * 130) * 4;
    cudaFuncSetAttribute(k_gemm1, cudaFuncAttributeMaxDynamicSharedMemorySize, SM1);
    cudaFuncSetAttribute(k_gemm2, cudaFuncAttributeMaxDynamicSharedMemorySize, SM2);
    cudaFuncSetAttribute(k_gemm3, cudaFuncAttributeMaxDynamicSharedMemorySize, SM3);

    // setup + degree + CSR
    k_zero<<<196, 256>>>();
    k_indeg<<<3125, 256>>>(dst);
    k_dinv_y0<<<3125, 256>>>(x);
    k_scan1<<<49, 1024>>>();
    k_scan3<<<49, 1024>>>();
    k_scatter<<<3125, 256>>>(src, dst);

    // layer 1
    k_agg1h<<<6250, 256>>>(y0h, ax);
    k_gemm1<<<782, 256, SM1>>>(ax, Wm1, Wl1, bm1, bl1, raw1);
    k_ew1<<<6250, 256>>>(gm1, hm1, gl1, hl1);

    // layer 2
    k_agg2h<<<6250, 256>>>(y1h, agg1);
    k_gemm2<<<782, 256, SM2>>>(agg1, Wm2, Wl2, bm2, bl2, raw2);

    // layer 3 (statfin2 folded into gemm3)
    k_gemm3<<<391, 256, SM3>>>(raw2, Wm3, Wl3, y3h, gm2, hm2, gl2, hl2);
    k_agg3f<<<6250, 256>>>(y3h, out_mu, bm3, bl3, out_ls);

    // decoder
    k_dec<<<25000, 256>>>(src, dst, out_mu, out_probs);
}

// round 9
// speedup vs baseline: 1.0811x; 1.0811x over previous
#include <cuda_runtime.h>
#include <cuda_fp16.h>

#define NN 50000
#define EE 800000

typedef unsigned long long ull;

__device__ __forceinline__ void ffma2(ull &d, ull a, ull b) {
    asm("fma.rn.f32x2 %0, %1, %2, %0;" : "+l"(d) : "l"(a), "l"(b));
}
__device__ __forceinline__ ull pack2(float a, float b) {
    ull r; asm("mov.b64 %0, {%1, %2};" : "=l"(r) : "f"(a), "f"(b)); return r;
}
__device__ __forceinline__ float lo2(ull u) { return __uint_as_float((unsigned)u); }
__device__ __forceinline__ float hi2(ull u) { return __uint_as_float((unsigned)(u >> 32)); }

// ---------------- scratch ----------------
__device__ float g_dinv[NN];
__device__ int   g_indeg[NN];
__device__ int   g_cur[NN];
__device__ int   g_off[NN + 1];
__device__ int   g_adj[EE];
__device__ int   g_bsum[64];

__device__ __half g_y0h[NN * 64];     // fp16 dinv*x
__device__ float  g_ax[NN * 64];
__device__ __half g_raw1h[NN * 128];  // fp16 gcn1 linear out
__device__ __half g_y1h[NN * 128];    // fp16 dinv*act1
__device__ float  g_agg1[NN * 128];
__device__ __half g_raw2h[NN * 256];  // fp16 gcn2 linear out
__device__ __half g_y3h[NN * 64];     // fp16 dinv*(act2@W3)
__device__ __half g_muh[NN * 32];     // fp16 mu for decoder

__device__ float g_ssum[512];
__device__ float g_ssq[512];

// ---------------- setup ----------------
__global__ void k_zero() {
    int i = blockIdx.x * blockDim.x + threadIdx.x;
    if (i < NN) { g_indeg[i] = 0; g_cur[i] = 0; }
    if (i < 512) { g_ssum[i] = 0.f; g_ssq[i] = 0.f; }
}

__global__ void k_indeg(const int* __restrict__ dst) {
    int e = blockIdx.x * blockDim.x + threadIdx.x;
    if (e < EE) atomicAdd(&g_indeg[dst[e]], 1);
}

__global__ void k_dinv_y0(const float* __restrict__ x) {
    int idx = blockIdx.x * blockDim.x + threadIdx.x;
    if (idx < NN * 16) {
        int row = idx >> 4;
        float d = rsqrtf((float)(g_indeg[row] + 1));
        if ((idx & 15) == 0) g_dinv[row] = d;
        float4 v = ((const float4*)x)[idx];
        __half2 h0 = __floats2half2_rn(v.x * d, v.y * d);
        __half2 h1 = __floats2half2_rn(v.z * d, v.w * d);
        ((uint2*)g_y0h)[idx] = make_uint2(*(unsigned*)&h0, *(unsigned*)&h1);
    }
}

// ---------------- CSR build ----------------
__global__ void k_scan1() {
    int i = blockIdx.x * 1024 + threadIdx.x;
    int v = (i < NN) ? g_indeg[i] : 0;
    int lane = threadIdx.x & 31, wid = threadIdx.x >> 5;
    int s = v;
    #pragma unroll
    for (int o = 1; o < 32; o <<= 1) {
        int t = __shfl_up_sync(~0u, s, o);
        if (lane >= o) s += t;
    }
    __shared__ int wsum[32];
    if (lane == 31) wsum[wid] = s;
    __syncthreads();
    if (wid == 0) {
        int ws = wsum[lane];
        #pragma unroll
        for (int o = 1; o < 32; o <<= 1) {
            int t = __shfl_up_sync(~0u, ws, o);
            if (lane >= o) ws += t;
        }
        wsum[lane] = ws;
    }
    __syncthreads();
    int incl = s + (wid > 0 ? wsum[wid - 1] : 0);
    if (i < NN) g_off[i + 1] = incl;
    if (threadIdx.x == 1023) g_bsum[blockIdx.x] = incl;
}

__global__ void k_scan3() {
    __shared__ int base;
    if (threadIdx.x == 0) {
        int acc = 0;
        for (int b = 0; b < blockIdx.x; b++) acc += g_bsum[b];
        base = acc;
    }
    __syncthreads();
    int i = blockIdx.x * 1024 + threadIdx.x;
    if (i < NN) g_off[i + 1] += base;
    if (i == 0) g_off[0] = 0;
}

__global__ void k_scatter(const int* __restrict__ src, const int* __restrict__ dst) {
    int e = blockIdx.x * blockDim.x + threadIdx.x;
    if (e < EE) {
        int d = dst[e];
        int p = g_off[d] + atomicAdd(&g_cur[d], 1);
        g_adj[p] = src[e];
    }
}

// ---------------- layer-1 aggregation: fp16 gather, fp32 accumulate (R7 form) ----------------
__global__ void k_agg1h(const __half* __restrict__ y, float* __restrict__ out) {
    int gw = (blockIdx.x * blockDim.x + threadIdx.x) >> 5;
    if (gw >= NN) return;
    int lane = threadIdx.x & 31;
    int beg = g_off[gw], end = g_off[gw + 1];
    float2 acc = __half22float2(*(const __half2*)(y + gw * 64 + lane * 2));
    for (int j = beg; j < end; j++) {
        int s = g_adj[j];
        float2 v = __half22float2(__ldg((const __half2*)(y + s * 64 + lane * 2)));
        acc.x += v.x; acc.y += v.y;
    }
    float d = g_dinv[gw];
    acc.x *= d; acc.y *= d;
    *(float2*)(out + gw * 64 + lane * 2) = acc;
}

// ---------------- layer-2 aggregation: fp16 gather (4 cols/lane) (R7 form) ----------------
__global__ void k_agg2h(const __half* __restrict__ y, float* __restrict__ out) {
    int gw = (blockIdx.x * blockDim.x + threadIdx.x) >> 5;
    if (gw >= NN) return;
    int lane = threadIdx.x & 31;
    int beg = g_off[gw], end = g_off[gw + 1];
    uint2 u0 = *(const uint2*)(y + (size_t)gw * 128 + lane * 4);
    float2 a01 = __half22float2(*(__half2*)&u0.x);
    float2 a23 = __half22float2(*(__half2*)&u0.y);
    float4 acc = make_float4(a01.x, a01.y, a23.x, a23.y);
    for (int j = beg; j < end; j++) {
        int s = g_adj[j];
        uint2 u = __ldg((const uint2*)(y + (size_t)s * 128 + lane * 4));
        float2 f01 = __half22float2(*(__half2*)&u.x);
        float2 f23 = __half22float2(*(__half2*)&u.y);
        acc.x += f01.x; acc.y += f01.y; acc.z += f23.x; acc.w += f23.y;
    }
    float d = g_dinv[gw];
    acc.x *= d; acc.y *= d; acc.z *= d; acc.w *= d;
    *(float4*)(out + (size_t)gw * 128 + lane * 4) = acc;
}

// ---------------- layer-3 aggregation (fp16 gather) + final epilogue + fp16 mu copy ----------------
__global__ void k_agg3f(const __half* __restrict__ y, float* __restrict__ out_mu,
                        const float* __restrict__ bm3, const float* __restrict__ bl3,
                        float* __restrict__ out_ls) {
    int gw = (blockIdx.x * blockDim.x + threadIdx.x) >> 5;
    if (gw >= NN) return;
    int lane = threadIdx.x & 31;
    int beg = g_off[gw], end = g_off[gw + 1];
    float2 acc = __half22float2(*(const __half2*)(y + gw * 64 + lane * 2));
    for (int j = beg; j < end; j++) {
        int s = g_adj[j];
        float2 v = __half22float2(__ldg((const __half2*)(y + s * 64 + lane * 2)));
        acc.x += v.x; acc.y += v.y;
    }
    float d = g_dinv[gw];
    acc.x *= d; acc.y *= d;
    int c = lane * 2;
    if (c < 32) {
        float m0 = acc.x + bm3[c];
        float m1 = acc.y + bm3[c + 1];
        out_mu[gw * 32 + c]     = m0;
        out_mu[gw * 32 + c + 1] = m1;
        __half2 hm = __floats2half2_rn(m0, m1);
        *(__half2*)(g_muh + gw * 32 + c) = hm;
    } else {
        out_ls[gw * 32 + c - 32] = fminf(acc.x + bl3[c - 32], 10.0f);
        out_ls[gw * 32 + c - 31] = fminf(acc.y + bl3[c - 31], 10.0f);
    }
}

// ---------------- layer-1 GEMM: row-pair FFMA2, fp16 output ----------------
__global__ void __launch_bounds__(256) k_gemm1(
        const float* __restrict__ A, const float* __restrict__ W1,
        const float* __restrict__ W2, const float* __restrict__ b1,
        const float* __restrict__ b2, __half* __restrict__ C) {
    extern __shared__ float sm1[];
    float* Ws  = sm1;
    float* Ast = sm1 + 8192;
    int tid = threadIdx.x;
    int row0 = blockIdx.x * 64;

    for (int i = tid; i < 1024; i += 256) {
        int k = i >> 4, q = i & 15;
        ((float4*)(Ws + k * 128))[q]      = ((const float4*)(W1 + k * 64))[q];
        ((float4*)(Ws + k * 128 + 64))[q] = ((const float4*)(W2 + k * 64))[q];
    }
    for (int i = tid; i < 1024; i += 256) {
        int r = i >> 4, q = i & 15;
        float4 v = make_float4(0.f, 0.f, 0.f, 0.f);
        if (row0 + r < NN) v = ((const float4*)(A + (row0 + r) * 64))[q];
        int k = q * 4;
        Ast[(k + 0) * 66 + r] = v.x;
        Ast[(k + 1) * 66 + r] = v.y;
        Ast[(k + 2) * 66 + r] = v.z;
        Ast[(k + 3) * 66 + r] = v.w;
    }
    __syncthreads();

    int tx = tid & 31, ty = tid >> 5;
    ull acc[4][4];
    #pragma unroll
    for (int i = 0; i < 4; i++)
        #pragma unroll
        for (int j = 0; j < 4; j++) acc[i][j] = 0ull;

    #pragma unroll 8
    for (int k = 0; k < 64; k++) {
        ull a2[4], w2[4];
        #pragma unroll
        for (int i = 0; i < 4; i++)
            a2[i] = *(const ull*)(Ast + k * 66 + ty * 8 + 2 * i);
        #pragma unroll
        for (int j = 0; j < 4; j++) {
            float w = Ws[k * 128 + tx + 32 * j];
            w2[j] = pack2(w, w);
        }
        #pragma unroll
        for (int i = 0; i < 4; i++)
            #pragma unroll
            for (int j = 0; j < 4; j++)
                ffma2(acc[i][j], a2[i], w2[j]);
    }

    float bb[4];
    bb[0] = b1[tx]; bb[1] = b1[tx + 32]; bb[2] = b2[tx]; bb[3] = b2[tx + 32];

    float ls[4] = {0.f, 0.f, 0.f, 0.f}, l2[4] = {0.f, 0.f, 0.f, 0.f};
    #pragma unroll
    for (int i = 0; i < 4; i++) {
        int r = row0 + ty * 8 + 2 * i;
        #pragma unroll
        for (int h = 0; h < 2; h++) {
            if (r + h < NN) {
                #pragma unroll
                for (int j = 0; j < 4; j++) {
                    float v = (h == 0 ? lo2(acc[i][j]) : hi2(acc[i][j])) + bb[j];
                    C[(size_t)(r + h) * 128 + tx + 32 * j] = __float2half_rn(v);
                    float sv = (j < 2) ? v : fmaxf(v, 0.f);
                    ls[j] += sv; l2[j] += sv * sv;
                }
            }
        }
    }
    __syncthreads();
    float* red = Ast;
    red[tid] = 0.f;
    __syncthreads();
    #pragma unroll
    for (int j = 0; j < 4; j++) {
        atomicAdd(&red[tx + 32 * j], ls[j]);
        atomicAdd(&red[128 + tx + 32 * j], l2[j]);
    }
    __syncthreads();
    if (tid < 128) {
        atomicAdd(&g_ssum[tid], red[tid]);
        atomicAdd(&g_ssq[tid], red[tid + 128]);
    }
}

// elementwise layer1: fp16 in -> BN/ReLU -> fp16 y1h, statfin folded
__global__ void k_ew1(const float* __restrict__ g1, const float* __restrict__ h1,
                      const float* __restrict__ g2, const float* __restrict__ h2) {
    __shared__ float sa[128], sb[128];
    int tid = threadIdx.x;
    if (tid < 128) {
        float m = g_ssum[tid] * (1.0f / NN);
        float v = g_ssq[tid] * (1.0f / NN) - m * m;
        float rstd = rsqrtf(v + 1e-5f);
        float gamma = (tid < 64) ? g1[tid] : g2[tid - 64];
        float beta  = (tid < 64) ? h1[tid] : h2[tid - 64];
        float a = gamma * rstd;
        sa[tid] = a;
        sb[tid] = beta - m * a;
    }
    __syncthreads();
    int idx = blockIdx.x * blockDim.x + tid;
    if (idx >= NN * 32) return;
    int r = idx >> 5;
    int c4 = (idx & 31) << 2;
    uint2 u = ((const uint2*)g_raw1h)[idx];
    float2 v01 = __half22float2(*(__half2*)&u.x);
    float2 v23 = __half22float2(*(__half2*)&u.y);
    float d = g_dinv[r];
    float o[4]; float vv[4] = {v01.x, v01.y, v23.x, v23.y};
    #pragma unroll
    for (int t = 0; t < 4; t++) {
        int c = c4 + t;
        float a = sa[c], b = sb[c];
        if (c4 < 64) o[t] = fmaxf(vv[t] * a + b, 0.f);
        else         o[t] = fmaxf(vv[t], 0.f) * a + b;
        o[t] *= d;
    }
    __half2 h0 = __floats2half2_rn(o[0], o[1]);
    __half2 h1v = __floats2half2_rn(o[2], o[3]);
    ((uint2*)g_y1h)[idx] = make_uint2(*(unsigned*)&h0, *(unsigned*)&h1v);
}

// ---------------- layer-2 GEMM: row-pair FFMA2, fp16 output ----------------
__global__ void __launch_bounds__(256) k_gemm2(
        const float* __restrict__ A, const float* __restrict__ W1,
        const float* __restrict__ W2, const float* __restrict__ b1,
        const float* __restrict__ b2, __half* __restrict__ C) {
    extern __shared__ float sm2[];
    float* Ws  = sm2;
    float* Ast = sm2 + 16384;
    int tid = threadIdx.x;
    int row0 = blockIdx.x * 64;

    for (int i = tid; i < 2048; i += 256) {
        int k = i >> 5, q = i & 31;
        ((float4*)(Ws + k * 256))[q]       = ((const float4*)(W1 + k * 128))[q];
        ((float4*)(Ws + k * 256 + 128))[q] = ((const float4*)(W2 + k * 128))[q];
    }
    for (int i = tid; i < 2048; i += 256) {
        int r = i >> 5, q = i & 31;
        float4 v = make_float4(0.f, 0.f, 0.f, 0.f);
        if (row0 + r < NN) v = ((const float4*)(A + (size_t)(row0 + r) * 128))[q];
        int k = q * 4;
        Ast[(k + 0) * 66 + r] = v.x;
        Ast[(k + 1) * 66 + r] = v.y;
        Ast[(k + 2) * 66 + r] = v.z;
        Ast[(k + 3) * 66 + r] = v.w;
    }
    __syncthreads();

    int tx = tid & 31, ty = tid >> 5;
    ull acc[4][8];
    #pragma unroll
    for (int i = 0; i < 4; i++)
        #pragma unroll
        for (int j = 0; j < 8; j++) acc[i][j] = 0ull;

    #pragma unroll 4
    for (int k = 0; k < 64; k++) {
        ull alo[4], ahi[4], w2[8];
        #pragma unroll
        for (int i = 0; i < 4; i++) {
            alo[i] = *(const ull*)(Ast + k * 66 + ty * 8 + 2 * i);
            ahi[i] = *(const ull*)(Ast + (64 + k) * 66 + ty * 8 + 2 * i);
        }
        #pragma unroll
        for (int j = 0; j < 8; j++) {
            float w = Ws[k * 256 + tx + 32 * j];
            w2[j] = pack2(w, w);
        }
        #pragma unroll
        for (int i = 0; i < 4; i++)
            #pragma unroll
            for (int j = 0; j < 8; j++)
                ffma2(acc[i][j], (j < 4 ? alo[i] : ahi[i]), w2[j]);
    }

    float bb[8];
    #pragma unroll
    for (int j = 0; j < 8; j++)
        bb[j] = (j < 4) ? b1[tx + 32 * j] : b2[tx + 32 * j - 128];

    float ls[8], l2[8];
    #pragma unroll
    for (int j = 0; j < 8; j++) { ls[j] = 0.f; l2[j] = 0.f; }
    #pragma unroll
    for (int i = 0; i < 4; i++) {
        int r = row0 + ty * 8 + 2 * i;
        #pragma unroll
        for (int h = 0; h < 2; h++) {
            if (r + h < NN) {
                #pragma unroll
                for (int j = 0; j < 8; j++) {
                    float v = (h == 0 ? lo2(acc[i][j]) : hi2(acc[i][j])) + bb[j];
                    C[(size_t)(r + h) * 256 + tx + 32 * j] = __float2half_rn(v);
                    float sv = (j < 4) ? v : fmaxf(v, 0.f);
                    ls[j] += sv; l2[j] += sv * sv;
                }
            }
        }
    }
    __syncthreads();
    float* red = Ast;
    red[tid] = 0.f; red[tid + 256] = 0.f;
    __syncthreads();
    #pragma unroll
    for (int j = 0; j < 8; j++) {
        atomicAdd(&red[tx + 32 * j], ls[j]);
        atomicAdd(&red[256 + tx + 32 * j], l2[j]);
    }
    __syncthreads();
    atomicAdd(&g_ssum[256 + tid], red[tid]);
    atomicAdd(&g_ssq[256 + tid], red[tid + 256]);
}

// ---------------- layer-3 GEMM: fp16 input (BN-on-load) + folded statfin, fp16 output ----------------
__global__ void __launch_bounds__(256) k_gemm3(
        const __half* __restrict__ raw2, const float* __restrict__ Wm3,
        const float* __restrict__ Wl3, __half* __restrict__ y3,
        const float* __restrict__ g1, const float* __restrict__ h1,
        const float* __restrict__ g2, const float* __restrict__ h2) {
    extern __shared__ float sm3[];
    float* sa  = sm3;
    float* sb  = sm3 + 256;
    float* Ws  = sm3 + 512;
    float* Ast = sm3 + 512 + 8192;
    int tid = threadIdx.x;
    int row0 = blockIdx.x * 128;

    {
        float m = g_ssum[256 + tid] * (1.0f / NN);
        float v = g_ssq[256 + tid] * (1.0f / NN) - m * m;
        float rstd = rsqrtf(v + 1e-5f);
        float gamma = (tid < 128) ? g1[tid] : g2[tid - 128];
        float beta  = (tid < 128) ? h1[tid] : h2[tid - 128];
        float a = gamma * rstd;
        sa[tid] = a;
        sb[tid] = beta - m * a;
    }

    for (int i = tid; i < 2048; i += 256) {
        int k = i >> 4, q = i & 15;
        float4 v = (q < 8) ? ((const float4*)(Wm3 + k * 32))[q]
                           : ((const float4*)(Wl3 + k * 32))[q - 8];
        ((float4*)(Ws + k * 64))[q] = v;
    }

    int tx = tid & 15, ty = tid >> 4;
    int half_c = (tx >= 8) ? 1 : 0;
    ull acc[4][4];
    #pragma unroll
    for (int i = 0; i < 4; i++)
        #pragma unroll
        for (int j = 0; j < 4; j++) acc[i][j] = 0ull;

    for (int kt = 0; kt < 128; kt += 32) {
        __syncthreads();
        for (int i = tid; i < 2048; i += 256) {
            int r = i >> 4, q = i & 15;
            int half = q >> 3, kk = (q & 7) << 2;
            uint2 u = make_uint2(0u, 0u);
            if (row0 + r < NN)
                u = ((const uint2*)(raw2 + (size_t)(row0 + r) * 256 + half * 128 + kt))[q & 7];
            float2 p01 = __half22float2(*(__half2*)&u.x);
            float2 p23 = __half22float2(*(__half2*)&u.y);
            float o[4]; float vv[4] = {p01.x, p01.y, p23.x, p23.y};
            #pragma unroll
            for (int t = 0; t < 4; t++) {
                int col = half * 128 + kt + kk + t;
                float a = sa[col], b = sb[col];
                if (half == 0) o[t] = fmaxf(vv[t] * a + b, 0.f);
                else           o[t] = fmaxf(vv[t], 0.f) * a + b;
                Ast[(half * 32 + kk + t) * 130 + r] = o[t];
            }
        }
        __syncthreads();
        #pragma unroll 8
        for (int k = 0; k < 32; k++) {
            float4 w = ((float4*)(Ws + (kt + k) * 64))[tx];
            ull w2[4];
            w2[0] = pack2(w.x, w.x); w2[1] = pack2(w.y, w.y);
            w2[2] = pack2(w.z, w.z); w2[3] = pack2(w.w, w.w);
            ull a2[4];
            #pragma unroll
            for (int i = 0; i < 4; i++)
                a2[i] = *(const ull*)(Ast + (half_c * 32 + k) * 130 + ty * 8 + 2 * i);
            #pragma unroll
            for (int i = 0; i < 4; i++)
                #pragma unroll
                for (int j = 0; j < 4; j++)
                    ffma2(acc[i][j], a2[i], w2[j]);
        }
    }
    #pragma unroll
    for (int i = 0; i < 4; i++) {
        int r = row0 + ty * 8 + 2 * i;
        if (r < NN) {
            float d = g_dinv[r];
            __half2 h0 = __floats2half2_rn(lo2(acc[i][0]) * d, lo2(acc[i][1]) * d);
            __half2 h1v = __floats2half2_rn(lo2(acc[i][2]) * d, lo2(acc[i][3]) * d);
            ((uint2*)(y3 + (size_t)r * 64))[tx] = make_uint2(*(unsigned*)&h0, *(unsigned*)&h1v);
        }
        if (r + 1 < NN) {
            float d = g_dinv[r + 1];
            __half2 h0 = __floats2half2_rn(hi2(acc[i][0]) * d, hi2(acc[i][1]) * d);
            __half2 h1v = __floats2half2_rn(hi2(acc[i][2]) * d, hi2(acc[i][3]) * d);
            ((uint2*)(y3 + (size_t)(r + 1) * 64))[tx] = make_uint2(*(unsigned*)&h0, *(unsigned*)&h1v);
        }
    }
}

// ---------------- decoder: fp16 mu, 4 lanes/edge ----------------
__global__ void k_dec(const int* __restrict__ src, const int* __restrict__ dst,
                      const __half* __restrict__ muh, float* __restrict__ probs) {
    int t = blockIdx.x * blockDim.x + threadIdx.x;  // EE*4 exactly
    int e = t >> 2, sub = t & 3;
    int s = src[e], d = dst[e];
    uint4 ua = __ldg((const uint4*)(muh + s * 32 + sub * 8));
    uint4 ub = __ldg((const uint4*)(muh + d * 32 + sub * 8));
    float p = 0.f;
    {
        float2 fa, fb;
        fa = __half22float2(*(__half2*)&ua.x); fb = __half22float2(*(__half2*)&ub.x);
        p += fa.x * fb.x + fa.y * fb.y;
        fa = __half22float2(*(__half2*)&ua.y); fb = __half22float2(*(__half2*)&ub.y);
        p += fa.x * fb.x + fa.y * fb.y;
        fa = __half22float2(*(__half2*)&ua.z); fb = __half22float2(*(__half2*)&ub.z);
        p += fa.x * fb.x + fa.y * fb.y;
        fa = __half22float2(*(__half2*)&ua.w); fb = __half22float2(*(__half2*)&ub.w);
        p += fa.x * fb.x + fa.y * fb.y;
    }
    p += __shfl_down_sync(~0u, p, 2);
    p += __shfl_down_sync(~0u, p, 1);
    if (sub == 0) probs[e] = 1.f / (1.f + expf(-p));
}

// ---------------- launch ----------------
extern "C" void kernel_launch(void* const* d_in, const int* in_sizes, int n_in,
                              void* d_out, int out_size) {
    const float* x   = (const float*)d_in[0];
    const int* ei    = (const int*)d_in[1];
    const int* src   = ei;
    const int* dst   = ei + EE;
    const float* Wm1 = (const float*)d_in[2];
    const float* bm1 = (const float*)d_in[3];
    const float* gm1 = (const float*)d_in[4];
    const float* hm1 = (const float*)d_in[5];
    const float* Wm2 = (const float*)d_in[6];
    const float* bm2 = (const float*)d_in[7];
    const float* gm2 = (const float*)d_in[8];
    const float* hm2 = (const float*)d_in[9];
    const float* Wm3 = (const float*)d_in[10];
    const float* bm3 = (const float*)d_in[11];
    const float* Wl1 = (const float*)d_in[12];
    const float* bl1 = (const float*)d_in[13];
    const float* gl1 = (const float*)d_in[14];
    const float* hl1 = (const float*)d_in[15];
    const float* Wl2 = (const float*)d_in[16];
    const float* bl2 = (const float*)d_in[17];
    const float* gl2 = (const float*)d_in[18];
    const float* hl2 = (const float*)d_in[19];
    const float* Wl3 = (const float*)d_in[20];
    const float* bl3 = (const float*)d_in[21];

    float* out = (float*)d_out;
    float* out_probs = out;
    float* out_mu = out + EE;
    float* out_ls = out + EE + NN * 32;

    float *ax, *agg1;
    __half *y0h, *raw1h, *y1h, *raw2h, *y3h, *muh;
    cudaGetSymbolAddress((void**)&y0h, g_y0h);
    cudaGetSymbolAddress((void**)&ax, g_ax);
    cudaGetSymbolAddress((void**)&raw1h, g_raw1h);
    cudaGetSymbolAddress((void**)&y1h, g_y1h);
    cudaGetSymbolAddress((void**)&agg1, g_agg1);
    cudaGetSymbolAddress((void**)&raw2h, g_raw2h);
    cudaGetSymbolAddress((void**)&y3h, g_y3h);
    cudaGetSymbolAddress((void**)&muh, g_muh);

    const int SM1 = (64 * 128 + 64 * 66) * 4;
    const int SM2 = (64 * 256 + 128 * 66) * 4;
    const int SM3 = (512 + 128 * 64 + 64 * 130) * 4;
    cudaFuncSetAttribute(k_gemm1, cudaFuncAttributeMaxDynamicSharedMemorySize, SM1);
    cudaFuncSetAttribute(k_gemm2, cudaFuncAttributeMaxDynamicSharedMemorySize, SM2);
    cudaFuncSetAttribute(k_gemm3, cudaFuncAttributeMaxDynamicSharedMemorySize, SM3);

    // setup + degree + CSR
    k_zero<<<196, 256>>>();
    k_indeg<<<3125, 256>>>(dst);
    k_dinv_y0<<<3125, 256>>>(x);
    k_scan1<<<49, 1024>>>();
    k_scan3<<<49, 1024>>>();
    k_scatter<<<3125, 256>>>(src, dst);

    // layer 1
    k_agg1h<<<6250, 256>>>(y0h, ax);
    k_gemm1<<<782, 256, SM1>>>(ax, Wm1, Wl1, bm1, bl1, raw1h);
    k_ew1<<<6250, 256>>>(gm1, hm1, gl1, hl1);

    // layer 2
    k_agg2h<<<6250, 256>>>(y1h, agg1);
    k_gemm2<<<782, 256, SM2>>>(agg1, Wm2, Wl2, bm2, bl2, raw2h);

    // layer 3
    k_gemm3<<<391, 256, SM3>>>(raw2h, Wm3, Wl3, y3h, gm2, hm2, gl2, hl2);
    k_agg3f<<<6250, 256>>>(y3h, out_mu, bm3, bl3, out_ls);

    // decoder (fp16 mu, 4 lanes/edge)
    k_dec<<<12500, 256>>>(src, dst, muh, out_probs);
}